// round 12
// baseline (speedup 1.0000x reference)
#include <cuda_runtime.h>
#include <cuda_bf16.h>

// ---------------- problem constants ----------------
#define HDIM 128
#define CC 512                       // N_CENTROIDS
#define SENT (CC*CC)                 // 262144
#define NK (SENT+1)                  // key space 262145
#define NSLOT (CC*(CC-1)/2 + 1)      // E_COARSE+1 = 130817
#define EMAX 800000
#define NMAX 100000
#define BMAX 2

// ---------------- scratch (__device__ globals: zero at load, re-zeroed by tail) ----
__device__ int   g_keys[EMAX];
__device__ int   g_order[EMAX];
__device__ __align__(16) int g_cntk[NK+3];
__device__ int   g_eoff[NK];
__device__ __align__(16) int g_cursor[NK+3];
__device__ int   g_slotkey[NSLOT];
__device__ int   g_rank_sent;
__device__ __align__(16) float g_nodesum[BMAX*CC*HDIM];
__device__ __align__(16) int g_ncnt[CC];
__device__ int   g_noff[CC];
__device__ __align__(16) int g_ncursor[CC];
__device__ int   g_nodeperm[NMAX];

#define SCAN_BLK 1024
#define NSCAN ((NK + SCAN_BLK - 1) / SCAN_BLK)     // 257
__device__ int g_bsumC[NSCAN];
__device__ int g_bsumP[NSCAN];

// ---------------- tail: restore scratch to zero for next replay ------------------
__global__ void rezero_kernel(int nodesum_elems) {
    int i = blockIdx.x * blockDim.x + threadIdx.x;
    int v = i * 4;
    const int4 z4 = make_int4(0, 0, 0, 0);
    if (v < NK) {
        *reinterpret_cast<int4*>(&g_cntk[v])   = z4;
        *reinterpret_cast<int4*>(&g_cursor[v]) = z4;
    }
    if (v < nodesum_elems)
        *reinterpret_cast<float4*>(&g_nodesum[v]) = make_float4(0.f, 0.f, 0.f, 0.f);
    if (v < CC) {
        *reinterpret_cast<int4*>(&g_ncnt[v])    = z4;
        *reinterpret_cast<int4*>(&g_ncursor[v]) = z4;
    }
}

// ---------------- launch 0: edge keys + per-key counts + node misc --------------
__global__ void edge_misc_kernel(const int* __restrict__ ei,
                                 const int* __restrict__ cci,
                                 const float* __restrict__ dist,
                                 float* __restrict__ out,
                                 int N, int E, size_t off3, size_t off4) {
    int e = blockIdx.x * blockDim.x + threadIdx.x;
    if (e < E) {
        int a = cci[ei[e]];
        int b = cci[ei[E + e]];
        int key;
        if (a == b) key = SENT;
        else {
            int lo = min(a, b), hi = max(a, b);
            key = lo * CC + hi;
        }
        g_keys[e] = key;
        atomicAdd(&g_cntk[key], 1);
    }
    if (e < N) {
        int c = cci[e];
        atomicAdd(&g_ncnt[c], 1);
        out[off3 + e] = (float)c;
        out[off4 + e] = dist[e];
    }
}

// ---------------- launch 1: scanA = per-block sums + node CSR scan --------------
__global__ void scanA_kernel() {
    int t = threadIdx.x;
    if (blockIdx.x < NSCAN) {
        int b0 = blockIdx.x * SCAN_BLK + t * 4;
        int c = 0, p = 0;
#pragma unroll
        for (int i = 0; i < 4; i++) {
            int k = b0 + i;
            if (k < NK) { int v = g_cntk[k]; c += v; p += (v > 0); }
        }
        __shared__ int sC[256], sP[256];
        sC[t] = c; sP[t] = p; __syncthreads();
        for (int s = 128; s > 0; s >>= 1) {
            if (t < s) { sC[t] += sC[t + s]; sP[t] += sP[t + s]; }
            __syncthreads();
        }
        if (t == 0) { g_bsumC[blockIdx.x] = sC[0]; g_bsumP[blockIdx.x] = sP[0]; }
    } else {
        // node CSR scan: 512 counts, 256 threads x 2 elements
        __shared__ int s[256];
        int a0 = g_ncnt[2 * t], a1 = g_ncnt[2 * t + 1];
        int pr = a0 + a1;
        s[t] = pr; __syncthreads();
        for (int st = 1; st < 256; st <<= 1) {
            int add = (t >= st) ? s[t - st] : 0;
            __syncthreads();
            s[t] += add;
            __syncthreads();
        }
        int excl = s[t] - pr;
        g_noff[2 * t]     = excl;
        g_noff[2 * t + 1] = excl + a0;
    }
}

// ---------------- launch 2: scanB = full key scan + node scatter ----------------
__global__ void scanB_kernel(const int* __restrict__ cci, int N) {
    int t = threadIdx.x;
    if (blockIdx.x < NSCAN) {
        __shared__ int sC[256], sP[256];
        int vc = (t < blockIdx.x) ? g_bsumC[t] : 0;   // blockIdx.x <= 256
        int vp = (t < blockIdx.x) ? g_bsumP[t] : 0;
        sC[t] = vc; sP[t] = vp; __syncthreads();
        for (int s = 128; s > 0; s >>= 1) {
            if (t < s) { sC[t] += sC[t + s]; sP[t] += sP[t + s]; }
            __syncthreads();
        }
        int baseC = sC[0], baseP = sP[0];
        __syncthreads();

        int b0 = blockIdx.x * SCAN_BLK + t * 4;
        int cv[4]; int c = 0, p = 0;
#pragma unroll
        for (int i = 0; i < 4; i++) {
            int k = b0 + i;
            cv[i] = (k < NK) ? g_cntk[k] : 0;
            c += cv[i]; p += (cv[i] > 0);
        }
        sC[t] = c; sP[t] = p; __syncthreads();
        for (int s = 1; s < 256; s <<= 1) {
            int ac = (t >= s) ? sC[t - s] : 0;
            int ap = (t >= s) ? sP[t - s] : 0;
            __syncthreads();
            sC[t] += ac; sP[t] += ap;
            __syncthreads();
        }
        int exC = baseC + sC[t] - c;
        int exP = baseP + sP[t] - p;
#pragma unroll
        for (int i = 0; i < 4; i++) {
            int k = b0 + i;
            if (k < NK) {
                g_eoff[k] = exC;
                if (cv[i] > 0 && k < SENT) g_slotkey[exP] = k;
                if (k == SENT) g_rank_sent = exP;
                exC += cv[i];
                exP += (cv[i] > 0);
            }
        }
    } else {
        int n = (blockIdx.x - NSCAN) * 256 + t;
        if (n < N) {
            int c = cci[n];
            int p = atomicAdd(&g_ncursor[c], 1);
            g_nodeperm[g_noff[c] + p] = n;
        }
    }
}

// ---------------- launch 3 (PROFILED): edge CSR scatter --------------------------
__global__ void scatter_kernel(int E) {
    int e = blockIdx.x * blockDim.x + threadIdx.x;
    if (e >= E) return;
    int k = g_keys[e];
    int p = atomicAdd(&g_cursor[k], 1);
    g_order[g_eoff[k] + p] = e;
}

// ---- launch 4: FUSED — mlp_pool blocks [0,mlpBlocks) + coarse_edge blocks rest --
// Overlaps the FMA-bound SGEMM with the DRAM-bound gather in one launch: the CTA
// scheduler interleaves blocks of both halves across the SM array.
#define TILE_R 128
#define KC 32
__global__ __launch_bounds__(256, 2)
void fused_mlp_edge_kernel(const float* __restrict__ x,
                           const float* __restrict__ dists,
                           const int*   __restrict__ cci,
                           const float* __restrict__ W,
                           const float* __restrict__ bias,
                           const float* __restrict__ ea,
                           float* __restrict__ out,
                           int N, int R, int E, int B,
                           size_t off1, size_t off2, int mlpBlocks) {
    __shared__ unsigned long long As2[TILE_R][KC + 1];
    __shared__ float Ws[KC][HDIM];
    __shared__ int   sSrc[TILE_R];
    __shared__ int   sKey[TILE_R];
    __shared__ float sDr[TILE_R];
    int tid = threadIdx.x;

    if (blockIdx.x < mlpBlocks) {
        // ================= MLP SGEMM + ReLU + sorted-run pooled RED =================
        int tx = tid & 15, ty = tid >> 4;
        int rowBase = blockIdx.x * TILE_R;

        if (tid < TILE_R) {
            int rr = rowBase + tid;
            if (rr < R) {
                int bb  = rr / N;
                int pos = rr - bb * N;
                int n   = g_nodeperm[pos];
                sSrc[tid] = bb * N + n;
                sKey[tid] = bb * CC + cci[n];
                sDr[tid]  = dists[n];
            } else { sSrc[tid] = -1; sKey[tid] = -1; sDr[tid] = 0.f; }
        }
        __syncthreads();

        unsigned long long accP[8][4];
#pragma unroll
        for (int i = 0; i < 8; i++)
#pragma unroll
            for (int j = 0; j < 4; j++) accP[i][j] = 0ull;

        for (int kt = 0; kt < HDIM; kt += KC) {
#pragma unroll
            for (int i = 0; i < (TILE_R * KC) / 256; i++) {
                int idx = tid + i * 256;
                int r = idx >> 5, cidx = idx & 31;
                int gr = sSrc[r];
                float v = (gr >= 0) ? x[(size_t)gr * HDIM + kt + cidx] : 0.f;
                unsigned long long packed;
                asm("mov.b64 %0, {%1, %1};" : "=l"(packed) : "f"(v));
                As2[r][cidx] = packed;
            }
#pragma unroll
            for (int i = 0; i < (KC * HDIM) / 256; i++) {
                int idx = tid + i * 256;
                int k = idx >> 7, h = idx & 127;
                Ws[k][h] = W[(size_t)(kt + k) * HDIM + h];
            }
            __syncthreads();
#pragma unroll
            for (int k = 0; k < KC; k++) {
                unsigned long long a2[8], wp[4];
#pragma unroll
                for (int i = 0; i < 8; i++) a2[i] = As2[ty * 8 + i][k];
#pragma unroll
                for (int j = 0; j < 4; j++)
                    wp[j] = *reinterpret_cast<const unsigned long long*>(&Ws[k][2 * tx + 32 * j]);
#pragma unroll
                for (int i = 0; i < 8; i++)
#pragma unroll
                    for (int j = 0; j < 4; j++)
                        asm("fma.rn.f32x2 %0, %1, %2, %0;"
                            : "+l"(accP[i][j]) : "l"(a2[i]), "l"(wp[j]));
            }
            __syncthreads();
        }

        const float* Wlast = W + (size_t)HDIM * HDIM;
        float bcol[8], wlcol[8];
#pragma unroll
        for (int j = 0; j < 4; j++) {
            int col = 2 * tx + 32 * j;
            bcol[2*j]   = bias[col];     bcol[2*j+1]  = bias[col + 1];
            wlcol[2*j]  = Wlast[col];    wlcol[2*j+1] = Wlast[col + 1];
        }
        float run[8];
#pragma unroll
        for (int j = 0; j < 8; j++) run[j] = 0.f;
        int runKey = -1;
#pragma unroll
        for (int i = 0; i < 8; i++) {
            int rl  = ty * 8 + i;
            int key = sKey[rl];
            if (key < 0) continue;
            if (key != runKey) {
                if (runKey >= 0) {
                    float* base = g_nodesum + (size_t)runKey * HDIM + 2 * tx;
#pragma unroll
                    for (int j = 0; j < 4; j++)
                        asm volatile("red.global.add.v2.f32 [%0], {%1, %2};"
                                     :: "l"(base + 32 * j), "f"(run[2*j]), "f"(run[2*j+1])
                                     : "memory");
                }
                runKey = key;
#pragma unroll
                for (int j = 0; j < 8; j++) run[j] = 0.f;
            }
            float dr = sDr[rl];
#pragma unroll
            for (int j = 0; j < 4; j++) {
                float vlo, vhi;
                asm("mov.b64 {%0, %1}, %2;" : "=f"(vlo), "=f"(vhi) : "l"(accP[i][j]));
                run[2*j]   += fmaxf(vlo + dr * wlcol[2*j]   + bcol[2*j],   0.f);
                run[2*j+1] += fmaxf(vhi + dr * wlcol[2*j+1] + bcol[2*j+1], 0.f);
            }
        }
        if (runKey >= 0) {
            float* base = g_nodesum + (size_t)runKey * HDIM + 2 * tx;
#pragma unroll
            for (int j = 0; j < 4; j++)
                asm volatile("red.global.add.v2.f32 [%0], {%1, %2};"
                             :: "l"(base + 32 * j), "f"(run[2*j]), "f"(run[2*j+1])
                             : "memory");
        }
    } else {
        // ============ coarse-edge gather-mean (2-deep pipeline, streaming) ==========
        int idx  = (blockIdx.x - mlpBlocks) * 256 + tid;
        int w    = idx >> 5;
        int lane = tid & 31;
        if (w >= NSLOT) return;
        int uvalid = g_rank_sent;
        float* cea = out + off1;
        float* ce  = out + off2;
        if (w < uvalid) {
            int k   = g_slotkey[w];
            int cnt = g_cntk[k];
            int off = g_eoff[k];
            float inv = 1.0f / (float)cnt;
            size_t bs = (size_t)E * (HDIM / 4);
            const float4* base = reinterpret_cast<const float4*>(ea) + lane;
            float4 acc0 = make_float4(0.f, 0.f, 0.f, 0.f);
            float4 acc1 = make_float4(0.f, 0.f, 0.f, 0.f);
            int e0 = g_order[off];
            const float4* p = base + (size_t)e0 * (HDIM / 4);
            float4 c0 = __ldcs(p);
            float4 c1 = (B > 1) ? __ldcs(p + bs) : make_float4(0.f, 0.f, 0.f, 0.f);
            for (int i = 1; i < cnt; i++) {
                int e1 = g_order[off + i];
                const float4* q = base + (size_t)e1 * (HDIM / 4);
                float4 n0 = __ldcs(q);
                float4 n1 = (B > 1) ? __ldcs(q + bs) : make_float4(0.f, 0.f, 0.f, 0.f);
                acc0.x += c0.x; acc0.y += c0.y; acc0.z += c0.z; acc0.w += c0.w;
                acc1.x += c1.x; acc1.y += c1.y; acc1.z += c1.z; acc1.w += c1.w;
                c0 = n0; c1 = n1;
            }
            acc0.x += c0.x; acc0.y += c0.y; acc0.z += c0.z; acc0.w += c0.w;
            acc1.x += c1.x; acc1.y += c1.y; acc1.z += c1.z; acc1.w += c1.w;

            acc0.x *= inv; acc0.y *= inv; acc0.z *= inv; acc0.w *= inv;
            *reinterpret_cast<float4*>(cea + ((size_t)w) * HDIM + lane * 4) = acc0;
            if (B > 1) {
                acc1.x *= inv; acc1.y *= inv; acc1.z *= inv; acc1.w *= inv;
                *reinterpret_cast<float4*>(cea + ((size_t)NSLOT + w) * HDIM + lane * 4) = acc1;
            }
            if (lane == 0) {
                ce[w]         = (float)(k >> 9);      // k / 512
                ce[NSLOT + w] = (float)(k & 511);     // k % 512
            }
        } else {
            float4 z = make_float4(0.f, 0.f, 0.f, 0.f);
            for (int bb = 0; bb < B; bb++)
                *reinterpret_cast<float4*>(cea + ((size_t)bb * NSLOT + w) * HDIM + lane * 4) = z;
            if (lane == 0) { ce[w] = -1.f; ce[NSLOT + w] = -1.f; }
        }
    }
}

// ---------------- launch 5: node_avg writeout -----------------------------------
__global__ void node_avg_kernel(float* __restrict__ out, int total) {
    int i = blockIdx.x * blockDim.x + threadIdx.x;
    if (i >= total) return;
    int c = (i >> 7) & (CC - 1);
    out[i] = g_nodesum[i] / fmaxf((float)g_ncnt[c], 1.f);
}

// ---------------- launcher -------------------------------------------------------
extern "C" void kernel_launch(void* const* d_in, const int* in_sizes, int n_in,
                              void* d_out, int out_size) {
    const float* x    = (const float*)d_in[0];
    const int*   ei   = (const int*)  d_in[1];
    const float* ea   = (const float*)d_in[2];
    // d_in[3] = scale (unused)
    const int*   cci  = (const int*)  d_in[4];
    const float* dist = (const float*)d_in[5];
    const float* W    = (const float*)d_in[6];
    const float* bias = (const float*)d_in[7];
    float* out = (float*)d_out;

    int N = in_sizes[4];
    int E = in_sizes[1] / 2;
    int B = (int)((long long)in_sizes[0] / ((long long)N * HDIM));
    int R = B * N;

    size_t off1 = (size_t)B * CC * HDIM;                 // coarse_edge_attrs
    size_t off2 = off1 + (size_t)B * NSLOT * HDIM;       // coarse_edges
    size_t off3 = off2 + 2 * (size_t)NSLOT;              // cci
    size_t off4 = off3 + (size_t)N;                      // distances

    int nodesum_elems = B * CC * HDIM;
    int nscat = (N + 255) / 256;
    int mlpBlocks  = (R + TILE_R - 1) / TILE_R;
    int edgeBlocks = (int)(((long long)NSLOT * 32 + 255) / 256);

    edge_misc_kernel<<<(E + 255) / 256, 256>>>(ei, cci, dist, out, N, E, off3, off4); // 0
    scanA_kernel<<<NSCAN + 1, 256>>>();                                               // 1
    scanB_kernel<<<NSCAN + nscat, 256>>>(cci, N);                                     // 2
    scatter_kernel<<<(E + 255) / 256, 256>>>(E);                                      // 3 (profiled)
    fused_mlp_edge_kernel<<<mlpBlocks + edgeBlocks, 256>>>(                           // 4
        x, dist, cci, W, bias, ea, out, N, R, E, B, off1, off2, mlpBlocks);
    node_avg_kernel<<<(nodesum_elems + 255) / 256, 256>>>(out, nodesum_elems);        // 5
    {
        int quads = (NK + 3) / 4;                       // rezero vector width 4
        rezero_kernel<<<(quads + 255) / 256, 256>>>(nodesum_elems);                   // 6
    }
}